// round 9
// baseline (speedup 1.0000x reference)
#include <cuda_runtime.h>
#include <cstdint>

#define N_B 8
#define NQ  1024
#define NK  1024
#define DD  1024
#define HH  16
#define DH  64
#define ELEMS (N_B*NQ*DD)   // 8388608

// Scratch. g_q: tf32 bits, pre-scaled by 1/8, [bh][row][e].
// g_k: tf32, [bh][key][e]. g_v: tf32, TRANSPOSED+PERMUTED [bh][e][permk(key)].
__device__ float g_q[HH*N_B*NQ*DH];
__device__ float g_k[HH*N_B*NK*DH];
__device__ float g_v[HH*N_B*NK*DH];
__device__ float g_o[N_B*NQ*DD];
// tf32-pre-rounded copies of GEMM inputs
__device__ float g_ar[ELEMS];
__device__ float g_br[ELEMS];
__device__ float g_cr[ELEMS];
__device__ float g_wr[4][DD*DD];

__device__ __forceinline__ uint32_t f2tf(float x) {
    uint32_t u; asm("cvt.rna.tf32.f32 %0, %1;" : "=r"(u) : "f"(x)); return u;
}

__device__ __forceinline__ void mma8(float* c, const uint32_t* a, const uint32_t* b) {
    asm volatile(
        "mma.sync.aligned.m16n8k8.row.col.f32.tf32.tf32.f32 "
        "{%0,%1,%2,%3}, {%4,%5,%6,%7}, {%8,%9}, {%0,%1,%2,%3};"
        : "+f"(c[0]), "+f"(c[1]), "+f"(c[2]), "+f"(c[3])
        : "r"(a[0]), "r"(a[1]), "r"(a[2]), "r"(a[3]), "r"(b[0]), "r"(b[1]));
}

__device__ __forceinline__ void ldsm4(uint32_t* d, uint32_t addr) {
    asm volatile("ldmatrix.sync.aligned.m8n8.x4.shared.b16 {%0,%1,%2,%3}, [%4];"
        : "=r"(d[0]), "=r"(d[1]), "=r"(d[2]), "=r"(d[3]) : "r"(addr));
}

__device__ __forceinline__ uint32_t s2u(const void* p) {
    return (uint32_t)__cvta_generic_to_shared(p);
}

__device__ __forceinline__ void cpa16(uint32_t dst, const void* src) {
    asm volatile("cp.async.cg.shared.global [%0], [%1], 16;" :: "r"(dst), "l"(src));
}
#define CPA_COMMIT asm volatile("cp.async.commit_group;")
#define CPA_WAIT0  asm volatile("cp.async.wait_group 0;")

__device__ __forceinline__ void pref_l2(const void* p) {
    asm volatile("prefetch.global.L2 [%0];" :: "l"(p));
}

// ---------------------------------------------------------------------------
// Fused pre-round: all 3 activations + 4 weights in one grid-stride launch
// ---------------------------------------------------------------------------
#define ACT4 (ELEMS/4)
#define W4   (DD*DD/4)
#define TOT4 (3*ACT4 + 4*W4)

__global__ __launch_bounds__(256) void round_all(
    const float4* __restrict__ q, const float4* __restrict__ k,
    const float4* __restrict__ v, const float4* __restrict__ wq,
    const float4* __restrict__ wk, const float4* __restrict__ wv,
    const float4* __restrict__ wo,
    float4* __restrict__ ar, float4* __restrict__ br, float4* __restrict__ cr,
    float4* __restrict__ wr)
{
    int i = blockIdx.x * blockDim.x + threadIdx.x;
    int stride = gridDim.x * blockDim.x;
    for (; i < TOT4; i += stride) {
        const float4* src; float4* dst; int j;
        if (i < 3 * ACT4) {
            int r = i / ACT4; j = i - r * ACT4;
            src = (r == 0) ? q : (r == 1) ? k : v;
            dst = (r == 0) ? ar : (r == 1) ? br : cr;
        } else {
            int t = i - 3 * ACT4;
            int r = t / W4; j = t - r * W4;
            src = (r == 0) ? wq : (r == 1) ? wk : (r == 2) ? wv : wo;
            dst = wr + r * W4;
        }
        float4 x = src[j];
        *(uint4*)(dst + j) = make_uint4(f2tf(x.x), f2tf(x.y), f2tf(x.z), f2tf(x.w));
    }
}

// ---------------------------------------------------------------------------
// GEMM core: C[m, r] = sum_d A[m,d] * W[r,d]  (tf32 mma, inputs pre-rounded)
// 128 threads, 4 warps, warp tile 64x64, block tile 128x128.
// 32-k-col stages, 2 smem buffers, ONE __syncthreads per stage.
// ---------------------------------------------------------------------------
#define GP2 36

__device__ __forceinline__ void gemm_body(
    const float* __restrict__ A, const float* __restrict__ W,
    float* __restrict__ out, int mode, int bx, int by, float* As0, float* Bs0)
{
    float (*As)[128 * GP2] = (float(*)[128 * GP2])As0;
    float (*Bs)[128 * GP2] = (float(*)[128 * GP2])Bs0;
    const int tid  = threadIdx.x;
    const int lane = tid & 31, warp = tid >> 5;
    const int wm = warp >> 1, wn = warp & 1;
    const int m0 = by * 128, n0 = bx * 128;

    float c[4][8][4];
#pragma unroll
    for (int a = 0; a < 4; a++)
#pragma unroll
        for (int b = 0; b < 8; b++)
#pragma unroll
            for (int i = 0; i < 4; i++) c[a][b][i] = 0.f;

    const int a_off = (wm * 64 + (lane & 15)) * GP2 + 4 * (lane >> 4);
    const int b_off = (wn * 64 + ((lane >> 4) * 8) + (lane & 7)) * GP2 + 4 * ((lane >> 3) & 1);

    // stage 32 k-cols (tile t) into slot s: 8 A-chunks + 8 B-chunks of 16B
    auto stage = [&](int t, int s) {
#pragma unroll
        for (int i = 0; i < 8; i++) {
            int ch = tid + i * 128;               // 0..1023
            int row = ch >> 3, col = (ch & 7) * 4;
            cpa16(s2u(As[s] + row * GP2 + col), A + (size_t)(m0 + row) * DD + t * 32 + col);
            cpa16(s2u(Bs[s] + row * GP2 + col), W + (size_t)(n0 + row) * DD + t * 32 + col);
        }
        CPA_COMMIT;
    };

    stage(0, 0);

    for (int kt = 0; kt < 32; kt++) {
        CPA_WAIT0;
        __syncthreads();
        if (kt + 1 < 32) stage(kt + 1, (kt + 1) & 1);

        const int s = kt & 1;
#pragma unroll
        for (int kk = 0; kk < 4; kk++) {
            uint32_t af[4][4];
#pragma unroll
            for (int mt = 0; mt < 4; mt++)
                ldsm4(af[mt], s2u(As[s] + a_off + mt * 16 * GP2 + kk * 8));
#pragma unroll
            for (int ntp = 0; ntp < 4; ntp++) {
                uint32_t bf[4];
                ldsm4(bf, s2u(Bs[s] + b_off + ntp * 16 * GP2 + kk * 8));
#pragma unroll
                for (int mt = 0; mt < 4; mt++) {
                    mma8(c[mt][ntp * 2 + 0], af[mt], &bf[0]);
                    mma8(c[mt][ntp * 2 + 1], af[mt], &bf[2]);
                }
            }
        }
    }

    // epilogue
#pragma unroll
    for (int mt = 0; mt < 4; mt++) {
        int mr = m0 + wm * 64 + mt * 16 + (lane >> 2);
#pragma unroll
        for (int nt = 0; nt < 8; nt++) {
            int nc = n0 + wn * 64 + nt * 8 + 2 * (lane & 3);
#pragma unroll
            for (int half = 0; half < 2; half++) {
                int m = mr + half * 8;
                float v0 = c[mt][nt][half * 2 + 0];
                float v1 = c[mt][nt][half * 2 + 1];
                if (mode == 1) {
                    *(float2*)(out + (size_t)m * DD + nc) = make_float2(v0, v1);
                } else if (mode == 0 || mode == 2) {
                    float sc = (mode == 0) ? 0.125f : 1.0f;
                    size_t idx = ((size_t)((nc >> 6) * N_B + (m >> 10)) << 16)
                               + (size_t)((m & 1023) * 64 + (nc & 63));
                    float2 w = make_float2(__uint_as_float(f2tf(v0 * sc)),
                                           __uint_as_float(f2tf(v1 * sc)));
                    *(float2*)(out + idx) = w;
                } else {
                    int key = m & 1023, n = m >> 10;
                    int lk = key & 7;
                    int kp = (key & ~7) | ((lk & 1) ? 4 + (lk >> 1) : (lk >> 1));
#pragma unroll
                    for (int cc = 0; cc < 2; cc++) {
                        int r = nc + cc, h = r >> 6, e = r & 63;
                        size_t idx = ((size_t)(h * N_B + n) << 16) + (size_t)e * NK + kp;
                        out[idx] = __uint_as_float(f2tf(cc ? v1 : v0));
                    }
                }
            }
        }
    }
}

__global__ __launch_bounds__(128, 2) void gemm_qkv(
    const float* __restrict__ Aq, const float* __restrict__ Ak, const float* __restrict__ Av,
    const float* __restrict__ Wq, const float* __restrict__ Wk, const float* __restrict__ Wv,
    float* __restrict__ oq, float* __restrict__ ok, float* __restrict__ ov)
{
    __shared__ float As[2][128 * GP2];
    __shared__ float Bs[2][128 * GP2];
    const int which = blockIdx.x >> 3;
    const int bx = blockIdx.x & 7;
    const float* A = (which == 0) ? Aq : (which == 1) ? Ak : Av;
    const float* W = (which == 0) ? Wq : (which == 1) ? Wk : Wv;
    float* out     = (which == 0) ? oq : (which == 1) ? ok : ov;
    const int mode = (which == 0) ? 0 : (which == 1) ? 2 : 3;
    gemm_body(A, W, out, mode, bx, blockIdx.y, &As[0][0], &Bs[0][0]);
}

__global__ __launch_bounds__(128, 2) void gemm_nt(
    const float* __restrict__ A, const float* __restrict__ W,
    float* __restrict__ out, int mode)
{
    __shared__ float As[2][128 * GP2];
    __shared__ float Bs[2][128 * GP2];
    gemm_body(A, W, out, mode, blockIdx.x, blockIdx.y, &As[0][0], &Bs[0][0]);
}

// ---------------------------------------------------------------------------
// Flash-style attention (exact R7 structure: interleaved exp/mask/P-mma).
// 256 threads, block = 128 q-rows of one (h,n), warp = 16 rows.
// ---------------------------------------------------------------------------
#define APAD 68
#define KV_FLOATS (64 * APAD)
#define BUF_FLOATS (2 * KV_FLOATS)
#define ATTN_SMEM (2 * BUF_FLOATS * (int)sizeof(float))

__global__ __launch_bounds__(256, 2) void attn(
    const float* __restrict__ gq, const float* __restrict__ gk,
    const float* __restrict__ gvt, const float* __restrict__ mask,
    float* __restrict__ go)
{
    extern __shared__ float smem[];
    const int tid  = threadIdx.x;
    const int lane = tid & 31, warp = tid >> 5;
    const int bh = blockIdx.y;
    const int q0 = blockIdx.x * 128;
    const size_t hb = (size_t)bh * (NQ * DH);

    uint32_t qa[8][4];
    {
        const float* qr0 = gq + hb + (size_t)(q0 + warp * 16 + (lane >> 2)) * DH;
        const float* qr1 = qr0 + 8 * DH;
#pragma unroll
        for (int kk = 0; kk < 8; kk++) {
            int c0 = kk * 8 + (lane & 3);
            qa[kk][0] = __float_as_uint(qr0[c0]);
            qa[kk][1] = __float_as_uint(qr1[c0]);
            qa[kk][2] = __float_as_uint(qr0[c0 + 4]);
            qa[kk][3] = __float_as_uint(qr1[c0 + 4]);
        }
    }

    float o[8][4];
#pragma unroll
    for (int et = 0; et < 8; et++)
#pragma unroll
        for (int i = 0; i < 4; i++) o[et][i] = 0.f;

    float Z0 = 0.f, Z1 = 0.f, S0 = 0.f, S1 = 0.f;

    const float* mbase = mask + (size_t)bh * ((size_t)NQ * NK)
                              + (size_t)(q0 + warp * 16 + (lane >> 2)) * NK;

    const int kb_off = ((lane >> 4) * 8 + (lane & 7)) * APAD + 4 * ((lane >> 3) & 1);

    const float* ksrc_b = gk + hb;
    const float* vsrc_b = gvt + hb;

    auto stage = [&](int kt, int b) {
        float* Kd = smem + b * BUF_FLOATS;
        float* Vd = Kd + KV_FLOATS;
        const float* ks = ksrc_b + (size_t)kt * 64 * DH;
        const float* vs = vsrc_b + kt * 64;
#pragma unroll
        for (int i = 0; i < 4; i++) {
            int cchunk = tid + i * 256;
            int row = cchunk >> 4, col = (cchunk & 15) * 4;
            cpa16(s2u(Kd + row * APAD + col), ks + row * 64 + col);
            cpa16(s2u(Vd + row * APAD + col), vs + (size_t)row * NK + col);
        }
        CPA_COMMIT;
    };

    if ((lane & 3) == 0) {
        const char* mp0 = (const char*)mbase;
        const char* mp1 = (const char*)(mbase + 8 * NK);
        pref_l2(mp0); pref_l2(mp0 + 128); pref_l2(mp1); pref_l2(mp1 + 128);
    }
    stage(0, 0);

    for (int kt = 0; kt < 16; kt++) {
        const int buf = kt & 1;
        CPA_WAIT0;
        __syncthreads();
        if (kt < 15) {
            stage(kt + 1, buf ^ 1);
            if ((lane & 3) == 0) {
                const char* mp0 = (const char*)(mbase + (kt + 1) * 64);
                const char* mp1 = (const char*)(mbase + (kt + 1) * 64 + 8 * NK);
                pref_l2(mp0); pref_l2(mp0 + 128); pref_l2(mp1); pref_l2(mp1 + 128);
            }
        }

        const float* Ks = smem + buf * BUF_FLOATS;
        const float* Vt = Ks + KV_FLOATS;

        // S = Q K^T (scale folded into Q)
        float s[8][4];
#pragma unroll
        for (int nt = 0; nt < 8; nt++)
#pragma unroll
            for (int i = 0; i < 4; i++) s[nt][i] = 0.f;
#pragma unroll
        for (int kk = 0; kk < 8; kk++) {
#pragma unroll
            for (int ntp = 0; ntp < 4; ntp++) {
                uint32_t bf[4];
                ldsm4(bf, s2u(Ks + kb_off + ntp * 16 * APAD + kk * 8));
                mma8(s[ntp * 2 + 0], qa[kk], &bf[0]);
                mma8(s[ntp * 2 + 1], qa[kk], &bf[2]);
            }
        }

        // interleaved: per 8-key slice, exp + mask + immediately its P-mmas
        const float2* mr0 = (const float2*)(mbase + kt * 64);
        const float2* mr1 = (const float2*)(mbase + kt * 64 + 8 * NK);
        float2 m0v[2], m1v[2];
        m0v[0] = mr0[lane & 3];       m1v[0] = mr1[lane & 3];
        m0v[1] = mr0[4 + (lane & 3)]; m1v[1] = mr1[4 + (lane & 3)];
#pragma unroll
        for (int kk = 0; kk < 8; kk++) {
            float2 m0 = m0v[kk & 1], m1 = m1v[kk & 1];
            if (kk < 6) {
                m0v[kk & 1] = mr0[(kk + 2) * 4 + (lane & 3)];
                m1v[kk & 1] = mr1[(kk + 2) * 4 + (lane & 3)];
            }
            float p00 = __expf(s[kk][0]), p01 = __expf(s[kk][1]);
            float p10 = __expf(s[kk][2]), p11 = __expf(s[kk][3]);
            Z0 += p00 + p01; Z1 += p10 + p11;
            float pm00 = p00 * m0.x, pm01 = p01 * m0.y;
            float pm10 = p10 * m1.x, pm11 = p11 * m1.y;
            S0 += pm00 + pm01; S1 += pm10 + pm11;
            uint32_t pa[4];
            pa[0] = f2tf(pm00); pa[1] = f2tf(pm10);
            pa[2] = f2tf(pm01); pa[3] = f2tf(pm11);
#pragma unroll
            for (int etp = 0; etp < 4; etp++) {
                uint32_t bf[4];
                ldsm4(bf, s2u(Vt + kb_off + etp * 16 * APAD + kk * 8));
                mma8(o[etp * 2 + 0], pa, &bf[0]);
                mma8(o[etp * 2 + 1], pa, &bf[2]);
            }
        }
    }

    Z0 += __shfl_xor_sync(0xffffffffu, Z0, 1); Z0 += __shfl_xor_sync(0xffffffffu, Z0, 2);
    Z1 += __shfl_xor_sync(0xffffffffu, Z1, 1); Z1 += __shfl_xor_sync(0xffffffffu, Z1, 2);
    S0 += __shfl_xor_sync(0xffffffffu, S0, 1); S0 += __shfl_xor_sync(0xffffffffu, S0, 2);
    S1 += __shfl_xor_sync(0xffffffffu, S1, 1); S1 += __shfl_xor_sync(0xffffffffu, S1, 2);

    float d0 = 1.f / (S0 + 1e-6f * Z0);
    float d1 = 1.f / (S1 + 1e-6f * Z1);

    const int n = bh & 7, h = bh >> 3;
    float* or0 = go + (size_t)(n * NQ + q0 + warp * 16 + (lane >> 2)) * DD + h * DH;
    float* or1 = or0 + 8 * DD;
#pragma unroll
    for (int et = 0; et < 8; et++) {
        int cc = et * 8 + 2 * (lane & 3);
        *(float2*)(or0 + cc) = make_float2(__uint_as_float(f2tf(o[et][0] * d0)),
                                           __uint_as_float(f2tf(o[et][1] * d0)));
        *(float2*)(or1 + cc) = make_float2(__uint_as_float(f2tf(o[et][2] * d1)),
                                           __uint_as_float(f2tf(o[et][3] * d1)));
    }
}

// ---------------------------------------------------------------------------
extern "C" void kernel_launch(void* const* d_in, const int* in_sizes, int n_in,
                              void* d_out, int out_size)
{
    const float* q    = (const float*)d_in[0];
    const float* k    = (const float*)d_in[1];
    const float* v    = (const float*)d_in[2];
    const float* mask = (const float*)d_in[3];
    const float* Wq   = (const float*)d_in[4];
    const float* Wk   = (const float*)d_in[5];
    const float* Wv   = (const float*)d_in[6];
    const float* Wo   = (const float*)d_in[7];
    float* out = (float*)d_out;

    float *pq, *pk, *pv, *po, *par, *pbr, *pcr, *pwr;
    cudaGetSymbolAddress((void**)&pq, g_q);
    cudaGetSymbolAddress((void**)&pk, g_k);
    cudaGetSymbolAddress((void**)&pv, g_v);
    cudaGetSymbolAddress((void**)&po, g_o);
    cudaGetSymbolAddress((void**)&par, g_ar);
    cudaGetSymbolAddress((void**)&pbr, g_br);
    cudaGetSymbolAddress((void**)&pcr, g_cr);
    cudaGetSymbolAddress((void**)&pwr, g_wr);

    cudaFuncSetAttribute(attn, cudaFuncAttributeMaxDynamicSharedMemorySize, ATTN_SMEM);

    round_all<<<1024, 256>>>((const float4*)q, (const float4*)k, (const float4*)v,
                             (const float4*)Wq, (const float4*)Wk, (const float4*)Wv,
                             (const float4*)Wo,
                             (float4*)par, (float4*)pbr, (float4*)pcr, (float4*)pwr);

    gemm_qkv<<<dim3(24, 64), 128>>>(par, pbr, pcr,
                                    pwr + 0 * DD * DD, pwr + 1 * DD * DD, pwr + 2 * DD * DD,
                                    pq, pk, pv);
    attn<<<dim3(8, 128), 256, ATTN_SMEM>>>(pq, pk, pv, mask, po);
    gemm_nt<<<dim3(8, 64), 128>>>(po, pwr + 3 * DD * DD, out, 1);
}

// round 10
// speedup vs baseline: 1.0249x; 1.0249x over previous
#include <cuda_runtime.h>
#include <cstdint>

#define N_B 8
#define NQ  1024
#define NK  1024
#define DD  1024
#define HH  16
#define DH  64
#define ELEMS (N_B*NQ*DD)   // 8388608

// Scratch. g_q: tf32 bits, pre-scaled by 1/8, [bh][row][e].
// g_k: tf32, [bh][key][e]. g_v: tf32, TRANSPOSED+PERMUTED [bh][e][permk(key)].
__device__ float g_q[HH*N_B*NQ*DH];
__device__ float g_k[HH*N_B*NK*DH];
__device__ float g_v[HH*N_B*NK*DH];
__device__ float g_o[N_B*NQ*DD];
// tf32-pre-rounded copies of GEMM inputs
__device__ float g_ar[ELEMS];
__device__ float g_br[ELEMS];
__device__ float g_cr[ELEMS];
__device__ float g_wr[4][DD*DD];

__device__ __forceinline__ uint32_t f2tf(float x) {
    uint32_t u; asm("cvt.rna.tf32.f32 %0, %1;" : "=r"(u) : "f"(x)); return u;
}

__device__ __forceinline__ void mma8(float* c, const uint32_t* a, const uint32_t* b) {
    asm volatile(
        "mma.sync.aligned.m16n8k8.row.col.f32.tf32.tf32.f32 "
        "{%0,%1,%2,%3}, {%4,%5,%6,%7}, {%8,%9}, {%0,%1,%2,%3};"
        : "+f"(c[0]), "+f"(c[1]), "+f"(c[2]), "+f"(c[3])
        : "r"(a[0]), "r"(a[1]), "r"(a[2]), "r"(a[3]), "r"(b[0]), "r"(b[1]));
}

__device__ __forceinline__ void ldsm4(uint32_t* d, uint32_t addr) {
    asm volatile("ldmatrix.sync.aligned.m8n8.x4.shared.b16 {%0,%1,%2,%3}, [%4];"
        : "=r"(d[0]), "=r"(d[1]), "=r"(d[2]), "=r"(d[3]) : "r"(addr));
}

__device__ __forceinline__ uint32_t s2u(const void* p) {
    return (uint32_t)__cvta_generic_to_shared(p);
}

__device__ __forceinline__ void cpa16(uint32_t dst, const void* src) {
    asm volatile("cp.async.cg.shared.global [%0], [%1], 16;" :: "r"(dst), "l"(src));
}
#define CPA_COMMIT asm volatile("cp.async.commit_group;")
#define CPA_WAIT0  asm volatile("cp.async.wait_group 0;")
#define CPA_WAIT1  asm volatile("cp.async.wait_group 1;")

__device__ __forceinline__ void pref_l2(const void* p) {
    asm volatile("prefetch.global.L2 [%0];" :: "l"(p));
}

// ---------------------------------------------------------------------------
// Fused pre-round: all 3 activations + 4 weights in one grid-stride launch
// ---------------------------------------------------------------------------
#define ACT4 (ELEMS/4)
#define W4   (DD*DD/4)
#define TOT4 (3*ACT4 + 4*W4)

__global__ __launch_bounds__(256) void round_all(
    const float4* __restrict__ q, const float4* __restrict__ k,
    const float4* __restrict__ v, const float4* __restrict__ wq,
    const float4* __restrict__ wk, const float4* __restrict__ wv,
    const float4* __restrict__ wo,
    float4* __restrict__ ar, float4* __restrict__ br, float4* __restrict__ cr,
    float4* __restrict__ wr)
{
    int i = blockIdx.x * blockDim.x + threadIdx.x;
    int stride = gridDim.x * blockDim.x;
    for (; i < TOT4; i += stride) {
        const float4* src; float4* dst; int j;
        if (i < 3 * ACT4) {
            int r = i / ACT4; j = i - r * ACT4;
            src = (r == 0) ? q : (r == 1) ? k : v;
            dst = (r == 0) ? ar : (r == 1) ? br : cr;
        } else {
            int t = i - 3 * ACT4;
            int r = t / W4; j = t - r * W4;
            src = (r == 0) ? wq : (r == 1) ? wk : (r == 2) ? wv : wo;
            dst = wr + r * W4;
        }
        float4 x = src[j];
        *(uint4*)(dst + j) = make_uint4(f2tf(x.x), f2tf(x.y), f2tf(x.z), f2tf(x.w));
    }
}

// ---------------------------------------------------------------------------
// GEMM core: C[m, r] = sum_d A[m,d] * W[r,d]  (tf32 mma, inputs pre-rounded)
// 256 threads, 8 warps, warp tile 64x32, block tile 128x128.
// 32-k-col stages, THREE smem buffers (dynamic), wait_group 1 => each staged
// tile has two compute periods to land. ONE __syncthreads per stage.
// ---------------------------------------------------------------------------
#define GP2 36
#define GEMM_STAGE_FLOATS (128 * GP2)
#define GEMM_SMEM (2 * 3 * GEMM_STAGE_FLOATS * (int)sizeof(float))   // 110592 B

__device__ __forceinline__ void gemm_body(
    const float* __restrict__ A, const float* __restrict__ W,
    float* __restrict__ out, int mode, int bx, int by)
{
    extern __shared__ float dsm[];
    float* Asb = dsm;                              // 3 stages of A
    float* Bsb = dsm + 3 * GEMM_STAGE_FLOATS;      // 3 stages of B
    const int tid  = threadIdx.x;
    const int lane = tid & 31, warp = tid >> 5;
    const int wm = warp >> 2, wn = warp & 3;
    const int m0 = by * 128, n0 = bx * 128;

    float c[4][4][4];
#pragma unroll
    for (int a = 0; a < 4; a++)
#pragma unroll
        for (int b = 0; b < 4; b++)
#pragma unroll
            for (int i = 0; i < 4; i++) c[a][b][i] = 0.f;

    const int a_off = (wm * 64 + (lane & 15)) * GP2 + 4 * (lane >> 4);
    const int b_off = (wn * 32 + ((lane >> 4) * 8) + (lane & 7)) * GP2 + 4 * ((lane >> 3) & 1);

    auto stage = [&](int t, int s) {
        float* As = Asb + s * GEMM_STAGE_FLOATS;
        float* Bs = Bsb + s * GEMM_STAGE_FLOATS;
#pragma unroll
        for (int i = 0; i < 4; i++) {
            int ch = tid + i * 256;               // 0..1023
            int row = ch >> 3, col = (ch & 7) * 4;
            cpa16(s2u(As + row * GP2 + col), A + (size_t)(m0 + row) * DD + t * 32 + col);
            cpa16(s2u(Bs + row * GP2 + col), W + (size_t)(n0 + row) * DD + t * 32 + col);
        }
        CPA_COMMIT;
    };

    stage(0, 0);
    stage(1, 1);

    for (int kt = 0; kt < 32; kt++) {
        CPA_WAIT1;            // stage(kt) complete; stage(kt+1) may be in flight
        __syncthreads();
        if (kt + 2 < 32) stage(kt + 2, (kt + 2) % 3);

        const float* As = Asb + (kt % 3) * GEMM_STAGE_FLOATS;
        const float* Bs = Bsb + (kt % 3) * GEMM_STAGE_FLOATS;
#pragma unroll
        for (int kk = 0; kk < 4; kk++) {
            uint32_t af[4][4];
#pragma unroll
            for (int mt = 0; mt < 4; mt++)
                ldsm4(af[mt], s2u(As + a_off + mt * 16 * GP2 + kk * 8));
#pragma unroll
            for (int ntp = 0; ntp < 2; ntp++) {
                uint32_t bf[4];
                ldsm4(bf, s2u(Bs + b_off + ntp * 16 * GP2 + kk * 8));
#pragma unroll
                for (int mt = 0; mt < 4; mt++) {
                    mma8(c[mt][ntp * 2 + 0], af[mt], &bf[0]);
                    mma8(c[mt][ntp * 2 + 1], af[mt], &bf[2]);
                }
            }
        }
    }

    // epilogue
#pragma unroll
    for (int mt = 0; mt < 4; mt++) {
        int mr = m0 + wm * 64 + mt * 16 + (lane >> 2);
#pragma unroll
        for (int nt = 0; nt < 4; nt++) {
            int nc = n0 + wn * 32 + nt * 8 + 2 * (lane & 3);
#pragma unroll
            for (int half = 0; half < 2; half++) {
                int m = mr + half * 8;
                float v0 = c[mt][nt][half * 2 + 0];
                float v1 = c[mt][nt][half * 2 + 1];
                if (mode == 1) {
                    *(float2*)(out + (size_t)m * DD + nc) = make_float2(v0, v1);
                } else if (mode == 0 || mode == 2) {
                    float sc = (mode == 0) ? 0.125f : 1.0f;
                    size_t idx = ((size_t)((nc >> 6) * N_B + (m >> 10)) << 16)
                               + (size_t)((m & 1023) * 64 + (nc & 63));
                    float2 w = make_float2(__uint_as_float(f2tf(v0 * sc)),
                                           __uint_as_float(f2tf(v1 * sc)));
                    *(float2*)(out + idx) = w;
                } else {
                    int key = m & 1023, n = m >> 10;
                    int lk = key & 7;
                    int kp = (key & ~7) | ((lk & 1) ? 4 + (lk >> 1) : (lk >> 1));
#pragma unroll
                    for (int cc = 0; cc < 2; cc++) {
                        int r = nc + cc, h = r >> 6, e = r & 63;
                        size_t idx = ((size_t)(h * N_B + n) << 16) + (size_t)e * NK + kp;
                        out[idx] = __uint_as_float(f2tf(cc ? v1 : v0));
                    }
                }
            }
        }
    }
}

__global__ __launch_bounds__(256, 2) void gemm_qkv(
    const float* __restrict__ Aq, const float* __restrict__ Ak, const float* __restrict__ Av,
    const float* __restrict__ Wq, const float* __restrict__ Wk, const float* __restrict__ Wv,
    float* __restrict__ oq, float* __restrict__ ok, float* __restrict__ ov)
{
    const int which = blockIdx.x >> 3;
    const int bx = blockIdx.x & 7;
    const float* A = (which == 0) ? Aq : (which == 1) ? Ak : Av;
    const float* W = (which == 0) ? Wq : (which == 1) ? Wk : Wv;
    float* out     = (which == 0) ? oq : (which == 1) ? ok : ov;
    const int mode = (which == 0) ? 0 : (which == 1) ? 2 : 3;
    gemm_body(A, W, out, mode, bx, blockIdx.y);
}

__global__ __launch_bounds__(256, 2) void gemm_nt(
    const float* __restrict__ A, const float* __restrict__ W,
    float* __restrict__ out, int mode)
{
    gemm_body(A, W, out, mode, blockIdx.x, blockIdx.y);
}

// ---------------------------------------------------------------------------
// Flash-style attention (exact R7 structure: interleaved exp/mask/P-mma).
// 256 threads, block = 128 q-rows of one (h,n), warp = 16 rows.
// ---------------------------------------------------------------------------
#define APAD 68
#define KV_FLOATS (64 * APAD)
#define BUF_FLOATS (2 * KV_FLOATS)
#define ATTN_SMEM (2 * BUF_FLOATS * (int)sizeof(float))

__global__ __launch_bounds__(256, 2) void attn(
    const float* __restrict__ gq, const float* __restrict__ gk,
    const float* __restrict__ gvt, const float* __restrict__ mask,
    float* __restrict__ go)
{
    extern __shared__ float smem[];
    const int tid  = threadIdx.x;
    const int lane = tid & 31, warp = tid >> 5;
    const int bh = blockIdx.y;
    const int q0 = blockIdx.x * 128;
    const size_t hb = (size_t)bh * (NQ * DH);

    uint32_t qa[8][4];
    {
        const float* qr0 = gq + hb + (size_t)(q0 + warp * 16 + (lane >> 2)) * DH;
        const float* qr1 = qr0 + 8 * DH;
#pragma unroll
        for (int kk = 0; kk < 8; kk++) {
            int c0 = kk * 8 + (lane & 3);
            qa[kk][0] = __float_as_uint(qr0[c0]);
            qa[kk][1] = __float_as_uint(qr1[c0]);
            qa[kk][2] = __float_as_uint(qr0[c0 + 4]);
            qa[kk][3] = __float_as_uint(qr1[c0 + 4]);
        }
    }

    float o[8][4];
#pragma unroll
    for (int et = 0; et < 8; et++)
#pragma unroll
        for (int i = 0; i < 4; i++) o[et][i] = 0.f;

    float Z0 = 0.f, Z1 = 0.f, S0 = 0.f, S1 = 0.f;

    const float* mbase = mask + (size_t)bh * ((size_t)NQ * NK)
                              + (size_t)(q0 + warp * 16 + (lane >> 2)) * NK;

    const int kb_off = ((lane >> 4) * 8 + (lane & 7)) * APAD + 4 * ((lane >> 3) & 1);

    const float* ksrc_b = gk + hb;
    const float* vsrc_b = gvt + hb;

    auto stage = [&](int kt, int b) {
        float* Kd = smem + b * BUF_FLOATS;
        float* Vd = Kd + KV_FLOATS;
        const float* ks = ksrc_b + (size_t)kt * 64 * DH;
        const float* vs = vsrc_b + kt * 64;
#pragma unroll
        for (int i = 0; i < 4; i++) {
            int cchunk = tid + i * 256;
            int row = cchunk >> 4, col = (cchunk & 15) * 4;
            cpa16(s2u(Kd + row * APAD + col), ks + row * 64 + col);
            cpa16(s2u(Vd + row * APAD + col), vs + (size_t)row * NK + col);
        }
        CPA_COMMIT;
    };

    if ((lane & 3) == 0) {
        const char* mp0 = (const char*)mbase;
        const char* mp1 = (const char*)(mbase + 8 * NK);
        pref_l2(mp0); pref_l2(mp0 + 128); pref_l2(mp1); pref_l2(mp1 + 128);
    }
    stage(0, 0);

    for (int kt = 0; kt < 16; kt++) {
        const int buf = kt & 1;
        CPA_WAIT0;
        __syncthreads();
        if (kt < 15) {
            stage(kt + 1, buf ^ 1);
            if ((lane & 3) == 0) {
                const char* mp0 = (const char*)(mbase + (kt + 1) * 64);
                const char* mp1 = (const char*)(mbase + (kt + 1) * 64 + 8 * NK);
                pref_l2(mp0); pref_l2(mp0 + 128); pref_l2(mp1); pref_l2(mp1 + 128);
            }
        }

        const float* Ks = smem + buf * BUF_FLOATS;
        const float* Vt = Ks + KV_FLOATS;

        // S = Q K^T (scale folded into Q)
        float s[8][4];
#pragma unroll
        for (int nt = 0; nt < 8; nt++)
#pragma unroll
            for (int i = 0; i < 4; i++) s[nt][i] = 0.f;
#pragma unroll
        for (int kk = 0; kk < 8; kk++) {
#pragma unroll
            for (int ntp = 0; ntp < 4; ntp++) {
                uint32_t bf[4];
                ldsm4(bf, s2u(Ks + kb_off + ntp * 16 * APAD + kk * 8));
                mma8(s[ntp * 2 + 0], qa[kk], &bf[0]);
                mma8(s[ntp * 2 + 1], qa[kk], &bf[2]);
            }
        }

        // interleaved: per 8-key slice, exp + mask + immediately its P-mmas
        const float2* mr0 = (const float2*)(mbase + kt * 64);
        const float2* mr1 = (const float2*)(mbase + kt * 64 + 8 * NK);
        float2 m0v[2], m1v[2];
        m0v[0] = mr0[lane & 3];       m1v[0] = mr1[lane & 3];
        m0v[1] = mr0[4 + (lane & 3)]; m1v[1] = mr1[4 + (lane & 3)];
#pragma unroll
        for (int kk = 0; kk < 8; kk++) {
            float2 m0 = m0v[kk & 1], m1 = m1v[kk & 1];
            if (kk < 6) {
                m0v[kk & 1] = mr0[(kk + 2) * 4 + (lane & 3)];
                m1v[kk & 1] = mr1[(kk + 2) * 4 + (lane & 3)];
            }
            float p00 = __expf(s[kk][0]), p01 = __expf(s[kk][1]);
            float p10 = __expf(s[kk][2]), p11 = __expf(s[kk][3]);
            Z0 += p00 + p01; Z1 += p10 + p11;
            float pm00 = p00 * m0.x, pm01 = p01 * m0.y;
            float pm10 = p10 * m1.x, pm11 = p11 * m1.y;
            S0 += pm00 + pm01; S1 += pm10 + pm11;
            uint32_t pa[4];
            pa[0] = f2tf(pm00); pa[1] = f2tf(pm10);
            pa[2] = f2tf(pm01); pa[3] = f2tf(pm11);
#pragma unroll
            for (int etp = 0; etp < 4; etp++) {
                uint32_t bf[4];
                ldsm4(bf, s2u(Vt + kb_off + etp * 16 * APAD + kk * 8));
                mma8(o[etp * 2 + 0], pa, &bf[0]);
                mma8(o[etp * 2 + 1], pa, &bf[2]);
            }
        }
    }

    Z0 += __shfl_xor_sync(0xffffffffu, Z0, 1); Z0 += __shfl_xor_sync(0xffffffffu, Z0, 2);
    Z1 += __shfl_xor_sync(0xffffffffu, Z1, 1); Z1 += __shfl_xor_sync(0xffffffffu, Z1, 2);
    S0 += __shfl_xor_sync(0xffffffffu, S0, 1); S0 += __shfl_xor_sync(0xffffffffu, S0, 2);
    S1 += __shfl_xor_sync(0xffffffffu, S1, 1); S1 += __shfl_xor_sync(0xffffffffu, S1, 2);

    float d0 = 1.f / (S0 + 1e-6f * Z0);
    float d1 = 1.f / (S1 + 1e-6f * Z1);

    const int n = bh & 7, h = bh >> 3;
    float* or0 = go + (size_t)(n * NQ + q0 + warp * 16 + (lane >> 2)) * DD + h * DH;
    float* or1 = or0 + 8 * DD;
#pragma unroll
    for (int et = 0; et < 8; et++) {
        int cc = et * 8 + 2 * (lane & 3);
        *(float2*)(or0 + cc) = make_float2(__uint_as_float(f2tf(o[et][0] * d0)),
                                           __uint_as_float(f2tf(o[et][1] * d0)));
        *(float2*)(or1 + cc) = make_float2(__uint_as_float(f2tf(o[et][2] * d1)),
                                           __uint_as_float(f2tf(o[et][3] * d1)));
    }
}

// ---------------------------------------------------------------------------
extern "C" void kernel_launch(void* const* d_in, const int* in_sizes, int n_in,
                              void* d_out, int out_size)
{
    const float* q    = (const float*)d_in[0];
    const float* k    = (const float*)d_in[1];
    const float* v    = (const float*)d_in[2];
    const float* mask = (const float*)d_in[3];
    const float* Wq   = (const float*)d_in[4];
    const float* Wk   = (const float*)d_in[5];
    const float* Wv   = (const float*)d_in[6];
    const float* Wo   = (const float*)d_in[7];
    float* out = (float*)d_out;

    float *pq, *pk, *pv, *po, *par, *pbr, *pcr, *pwr;
    cudaGetSymbolAddress((void**)&pq, g_q);
    cudaGetSymbolAddress((void**)&pk, g_k);
    cudaGetSymbolAddress((void**)&pv, g_v);
    cudaGetSymbolAddress((void**)&po, g_o);
    cudaGetSymbolAddress((void**)&par, g_ar);
    cudaGetSymbolAddress((void**)&pbr, g_br);
    cudaGetSymbolAddress((void**)&pcr, g_cr);
    cudaGetSymbolAddress((void**)&pwr, g_wr);

    cudaFuncSetAttribute(attn, cudaFuncAttributeMaxDynamicSharedMemorySize, ATTN_SMEM);
    cudaFuncSetAttribute(gemm_qkv, cudaFuncAttributeMaxDynamicSharedMemorySize, GEMM_SMEM);
    cudaFuncSetAttribute(gemm_nt,  cudaFuncAttributeMaxDynamicSharedMemorySize, GEMM_SMEM);

    round_all<<<1024, 256>>>((const float4*)q, (const float4*)k, (const float4*)v,
                             (const float4*)Wq, (const float4*)Wk, (const float4*)Wv,
                             (const float4*)Wo,
                             (float4*)par, (float4*)pbr, (float4*)pcr, (float4*)pwr);

    gemm_qkv<<<dim3(24, 64), 256, GEMM_SMEM>>>(par, pbr, pcr,
                                    pwr + 0 * DD * DD, pwr + 1 * DD * DD, pwr + 2 * DD * DD,
                                    pq, pk, pv);
    attn<<<dim3(8, 128), 256, ATTN_SMEM>>>(pq, pk, pv, mask, po);
    gemm_nt<<<dim3(8, 64), 256, GEMM_SMEM>>>(po, pwr + 3 * DD * DD, out, 1);
}

// round 11
// speedup vs baseline: 1.6654x; 1.6249x over previous
#include <cuda_runtime.h>
#include <cuda_fp16.h>
#include <cstdint>

#define N_B 8
#define NQ  1024
#define NK  1024
#define DD  1024
#define HH  16
#define DH  64
#define ELEMS (N_B*NQ*DD)   // 8388608

// Scratch (fp16). g_q: pre-scaled by 1/8, [bh][row][e]. g_k: [bh][key][e].
// g_v: TRANSPOSED [bh][e][key]. g_o: [n][q][h*64+e].
__device__ __half g_q[HH*N_B*NQ*DH];
__device__ __half g_k[HH*N_B*NK*DH];
__device__ __half g_v[HH*N_B*NK*DH];
__device__ __half g_o[ELEMS];
// fp16 copies of GEMM inputs
__device__ __half g_ar[ELEMS];
__device__ __half g_br[ELEMS];
__device__ __half g_cr[ELEMS];
__device__ __half g_wr[4][DD*DD];

__device__ __forceinline__ void mma16(float* c, const uint32_t* a, const uint32_t* b) {
    asm volatile(
        "mma.sync.aligned.m16n8k16.row.col.f32.f16.f16.f32 "
        "{%0,%1,%2,%3}, {%4,%5,%6,%7}, {%8,%9}, {%0,%1,%2,%3};"
        : "+f"(c[0]), "+f"(c[1]), "+f"(c[2]), "+f"(c[3])
        : "r"(a[0]), "r"(a[1]), "r"(a[2]), "r"(a[3]), "r"(b[0]), "r"(b[1]));
}

__device__ __forceinline__ void ldsm4(uint32_t* d, uint32_t addr) {
    asm volatile("ldmatrix.sync.aligned.m8n8.x4.shared.b16 {%0,%1,%2,%3}, [%4];"
        : "=r"(d[0]), "=r"(d[1]), "=r"(d[2]), "=r"(d[3]) : "r"(addr));
}

__device__ __forceinline__ uint32_t s2u(const void* p) {
    return (uint32_t)__cvta_generic_to_shared(p);
}

__device__ __forceinline__ void cpa16(uint32_t dst, const void* src) {
    asm volatile("cp.async.cg.shared.global [%0], [%1], 16;" :: "r"(dst), "l"(src));
}
#define CPA_COMMIT asm volatile("cp.async.commit_group;")
#define CPA_WAIT0  asm volatile("cp.async.wait_group 0;")

__device__ __forceinline__ void pref_l2(const void* p) {
    asm volatile("prefetch.global.L2 [%0];" :: "l"(p));
}

// pack two f32 -> fp16x2 register (lo = first arg)
__device__ __forceinline__ uint32_t packh2(float lo, float hi) {
    uint32_t r; asm("cvt.rn.f16x2.f32 %0, %1, %2;" : "=r"(r) : "f"(hi), "f"(lo));
    return r;
}

// ---------------------------------------------------------------------------
// Fused pre-convert fp32 -> fp16: 3 activations + 4 weights in one launch
// ---------------------------------------------------------------------------
#define ACT4 (ELEMS/4)
#define W4   (DD*DD/4)
#define TOT4 (3*ACT4 + 4*W4)

__global__ __launch_bounds__(256) void round_all(
    const float4* __restrict__ q, const float4* __restrict__ k,
    const float4* __restrict__ v, const float4* __restrict__ wq,
    const float4* __restrict__ wk, const float4* __restrict__ wv,
    const float4* __restrict__ wo,
    __half2* __restrict__ ar, __half2* __restrict__ br, __half2* __restrict__ cr,
    __half2* __restrict__ wr)
{
    int i = blockIdx.x * blockDim.x + threadIdx.x;
    int stride = gridDim.x * blockDim.x;
    for (; i < TOT4; i += stride) {
        const float4* src; __half2* dst; int j;
        if (i < 3 * ACT4) {
            int r = i / ACT4; j = i - r * ACT4;
            src = (r == 0) ? q : (r == 1) ? k : v;
            dst = (r == 0) ? ar : (r == 1) ? br : cr;
        } else {
            int t = i - 3 * ACT4;
            int r = t / W4; j = t - r * W4;
            src = (r == 0) ? wq : (r == 1) ? wk : (r == 2) ? wv : wo;
            dst = wr + r * (DD * DD / 2);
        }
        float4 x = src[j];
        __half2 h0 = __floats2half2_rn(x.x, x.y);
        __half2 h1 = __floats2half2_rn(x.z, x.w);
        uint2 u; u.x = *(uint32_t*)&h0; u.y = *(uint32_t*)&h1;
        *(uint2*)(dst + 2 * j) = u;
    }
}

// ---------------------------------------------------------------------------
// fp16 GEMM: C[m,r] = sum_d A[m,d]*W[r,d]  (m16n8k16, f32 accum)
// 256 threads, 8 warps, warp tile 64x32, block tile 128x128.
// 64-k-col stages, 2 smem buffers, ONE __syncthreads per stage.
// modes: 0 Q head-major *0.125 fp16 | 1 row-major fp32 | 2 K head-major fp16
//        3 V transposed fp16
// ---------------------------------------------------------------------------
#define PH 72   // 144B pitch: 9 x 16B -> ldmatrix conflict-free, cp.async aligned
#define GSTG (128 * PH)                    // halfs per array per stage
#define GEMM_SMEM (2 * 2 * GSTG * 2)       // 73728 bytes

__device__ __forceinline__ void gemm_body(
    const __half* __restrict__ A, const __half* __restrict__ W,
    void* __restrict__ out, int mode, int bx, int by)
{
    extern __shared__ __half hsm[];
    __half* Asb = hsm;
    __half* Bsb = hsm + 2 * GSTG;
    const int tid  = threadIdx.x;
    const int lane = tid & 31, warp = tid >> 5;
    const int wm = warp >> 2, wn = warp & 3;
    const int m0 = by * 128, n0 = bx * 128;

    float c[4][4][4];
#pragma unroll
    for (int a = 0; a < 4; a++)
#pragma unroll
        for (int b = 0; b < 4; b++)
#pragma unroll
            for (int i = 0; i < 4; i++) c[a][b][i] = 0.f;

    const int a_off = (wm * 64 + (lane & 15)) * PH + ((lane >> 4) << 3);
    const int b_off = (wn * 32 + (lane & 7) + ((lane >> 4) << 3)) * PH + (lane & 8);

    // stage 64 k-cols (tile t, 128B/row) into slot s
    auto stage = [&](int t, int s) {
        __half* As = Asb + s * GSTG;
        __half* Bs = Bsb + s * GSTG;
#pragma unroll
        for (int i = 0; i < 4; i++) {
            int ch = tid + i * 256;               // 0..1023
            int row = ch >> 3, c16 = (ch & 7) * 8;
            cpa16(s2u(As + row * PH + c16), A + (size_t)(m0 + row) * DD + t * 64 + c16);
            cpa16(s2u(Bs + row * PH + c16), W + (size_t)(n0 + row) * DD + t * 64 + c16);
        }
        CPA_COMMIT;
    };

    stage(0, 0);

    for (int kt = 0; kt < 16; kt++) {
        CPA_WAIT0;
        __syncthreads();
        if (kt + 1 < 16) stage(kt + 1, (kt + 1) & 1);

        const __half* As = Asb + (kt & 1) * GSTG;
        const __half* Bs = Bsb + (kt & 1) * GSTG;
#pragma unroll
        for (int kk = 0; kk < 4; kk++) {
            uint32_t af[4][4];
#pragma unroll
            for (int mt = 0; mt < 4; mt++)
                ldsm4(af[mt], s2u(As + a_off + mt * 16 * PH + kk * 16));
#pragma unroll
            for (int ng = 0; ng < 2; ng++) {
                uint32_t bf[4];
                ldsm4(bf, s2u(Bs + b_off + ng * 16 * PH + kk * 16));
#pragma unroll
                for (int mt = 0; mt < 4; mt++) {
                    mma16(c[mt][ng * 2 + 0], af[mt], &bf[0]);
                    mma16(c[mt][ng * 2 + 1], af[mt], &bf[2]);
                }
            }
        }
    }

    // epilogue
#pragma unroll
    for (int mt = 0; mt < 4; mt++) {
        int mr = m0 + wm * 64 + mt * 16 + (lane >> 2);
#pragma unroll
        for (int nt = 0; nt < 4; nt++) {
            int nc = n0 + wn * 32 + nt * 8 + 2 * (lane & 3);
#pragma unroll
            for (int half = 0; half < 2; half++) {
                int m = mr + half * 8;
                float v0 = c[mt][nt][half * 2 + 0];
                float v1 = c[mt][nt][half * 2 + 1];
                if (mode == 1) {
                    *(float2*)((float*)out + (size_t)m * DD + nc) = make_float2(v0, v1);
                } else if (mode == 0 || mode == 2) {
                    float sc = (mode == 0) ? 0.125f : 1.0f;
                    size_t idx = ((size_t)((nc >> 6) * N_B + (m >> 10)) << 16)
                               + (size_t)((m & 1023) * 64 + (nc & 63));
                    *(__half2*)((__half*)out + idx) = __floats2half2_rn(v0 * sc, v1 * sc);
                } else { // mode 3: V transposed [bh][e][key]
                    int key = m & 1023, n = m >> 10;
#pragma unroll
                    for (int cc = 0; cc < 2; cc++) {
                        int r = nc + cc, h = r >> 6, e = r & 63;
                        size_t idx = ((size_t)(h * N_B + n) << 16) + (size_t)e * NK + key;
                        ((__half*)out)[idx] = __float2half_rn(cc ? v1 : v0);
                    }
                }
            }
        }
    }
}

__global__ __launch_bounds__(256, 2) void gemm_qkv(
    const __half* __restrict__ Aq, const __half* __restrict__ Ak, const __half* __restrict__ Av,
    const __half* __restrict__ Wq, const __half* __restrict__ Wk, const __half* __restrict__ Wv,
    __half* __restrict__ oq, __half* __restrict__ ok, __half* __restrict__ ov)
{
    const int which = blockIdx.x >> 3;
    const int bx = blockIdx.x & 7;
    const __half* A = (which == 0) ? Aq : (which == 1) ? Ak : Av;
    const __half* W = (which == 0) ? Wq : (which == 1) ? Wk : Wv;
    __half* out    = (which == 0) ? oq : (which == 1) ? ok : ov;
    const int mode = (which == 0) ? 0 : (which == 1) ? 2 : 3;
    gemm_body(A, W, out, mode, bx, blockIdx.y);
}

__global__ __launch_bounds__(256, 2) void gemm_out(
    const __half* __restrict__ A, const __half* __restrict__ W,
    float* __restrict__ out)
{
    gemm_body(A, W, out, 1, blockIdx.x, blockIdx.y);
}

// ---------------------------------------------------------------------------
// Flash-style attention, fp16 mma (m16n8k16), no online max.
// 256 threads, block = 128 q-rows of one (h,n), warp = 16 rows.
// P packed straight from C-fragments (consecutive-k pairs) — no V permutation.
// ---------------------------------------------------------------------------
#define PH2 72
#define KVH (64 * PH2)

__global__ __launch_bounds__(256, 2) void attn(
    const __half* __restrict__ gq, const __half* __restrict__ gk,
    const __half* __restrict__ gvt, const float* __restrict__ mask,
    __half* __restrict__ go)
{
    __shared__ __half Ksm[2][KVH];
    __shared__ __half Vsm[2][KVH];
    const int tid  = threadIdx.x;
    const int lane = tid & 31, warp = tid >> 5;
    const int bh = blockIdx.y;
    const int q0 = blockIdx.x * 128;
    const size_t hb = (size_t)bh * (NQ * DH);

    // Q fragments direct from global (fp16, pre-scaled)
    uint32_t qa[4][4];
    {
        const __half* qr0 = gq + hb + (size_t)(q0 + warp * 16 + (lane >> 2)) * DH;
        const __half* qr1 = qr0 + 8 * DH;
        const int cl = 2 * (lane & 3);
#pragma unroll
        for (int kk = 0; kk < 4; kk++) {
            qa[kk][0] = *(const uint32_t*)(qr0 + kk * 16 + cl);
            qa[kk][1] = *(const uint32_t*)(qr1 + kk * 16 + cl);
            qa[kk][2] = *(const uint32_t*)(qr0 + kk * 16 + cl + 8);
            qa[kk][3] = *(const uint32_t*)(qr1 + kk * 16 + cl + 8);
        }
    }

    float o[8][4];
#pragma unroll
    for (int et = 0; et < 8; et++)
#pragma unroll
        for (int i = 0; i < 4; i++) o[et][i] = 0.f;

    float Z0 = 0.f, Z1 = 0.f, S0 = 0.f, S1 = 0.f;

    const float* mbase = mask + (size_t)bh * ((size_t)NQ * NK)
                              + (size_t)(q0 + warp * 16 + (lane >> 2)) * NK;

    const int kb_off = ((lane & 7) + ((lane >> 4) << 3)) * PH2 + (lane & 8);

    const __half* ksrc_b = gk + hb;
    const __half* vsrc_b = gvt + hb;

    auto stage = [&](int kt, int b) {
        __half* Kd = Ksm[b];
        __half* Vd = Vsm[b];
        const __half* ks = ksrc_b + (size_t)kt * 64 * DH;
        const __half* vs = vsrc_b + kt * 64;
#pragma unroll
        for (int i = 0; i < 2; i++) {
            int ch = tid + i * 256;               // 0..511
            int row = ch >> 3, c16 = (ch & 7) * 8;
            cpa16(s2u(Kd + row * PH2 + c16), ks + row * DH + c16);
            cpa16(s2u(Vd + row * PH2 + c16), vs + (size_t)row * NK + c16);
        }
        CPA_COMMIT;
    };

    if ((lane & 3) == 0) {
        const char* mp0 = (const char*)mbase;
        const char* mp1 = (const char*)(mbase + 8 * NK);
        pref_l2(mp0); pref_l2(mp0 + 128); pref_l2(mp1); pref_l2(mp1 + 128);
    }
    stage(0, 0);

    for (int kt = 0; kt < 16; kt++) {
        const int buf = kt & 1;
        CPA_WAIT0;
        __syncthreads();
        if (kt < 15) {
            stage(kt + 1, buf ^ 1);
            if ((lane & 3) == 0) {
                const char* mp0 = (const char*)(mbase + (kt + 1) * 64);
                const char* mp1 = (const char*)(mbase + (kt + 1) * 64 + 8 * NK);
                pref_l2(mp0); pref_l2(mp0 + 128); pref_l2(mp1); pref_l2(mp1 + 128);
            }
        }

        const __half* Ks = Ksm[buf];
        const __half* Vt = Vsm[buf];

        // S = Q K^T (scale folded into Q): 4 k16-chunks over d=64
        float s[8][4];
#pragma unroll
        for (int nt = 0; nt < 8; nt++)
#pragma unroll
            for (int i = 0; i < 4; i++) s[nt][i] = 0.f;
#pragma unroll
        for (int kk = 0; kk < 4; kk++) {
#pragma unroll
            for (int ntp = 0; ntp < 4; ntp++) {
                uint32_t bf[4];
                ldsm4(bf, s2u(Ks + kb_off + ntp * 16 * PH2 + kk * 16));
                mma16(s[ntp * 2 + 0], qa[kk], &bf[0]);
                mma16(s[ntp * 2 + 1], qa[kk], &bf[2]);
            }
        }

        // PV in 4 k16-slices; exp/mask for 2 n-groups per slice, pack -> A-frag
        const float2* mr0 = (const float2*)(mbase + kt * 64);
        const float2* mr1 = (const float2*)(mbase + kt * 64 + 8 * NK);
        const int ml = lane & 3;
        float2 mA0 = mr0[ml], mA1 = mr0[4 + ml];
        float2 mB0 = mr1[ml], mB1 = mr1[4 + ml];
#pragma unroll
        for (int kk = 0; kk < 4; kk++) {
            uint32_t vb[4][4];
#pragma unroll
            for (int etp = 0; etp < 4; etp++)
                ldsm4(vb[etp], s2u(Vt + kb_off + etp * 16 * PH2 + kk * 16));

            float2 a0 = mA0, a1 = mA1, b0 = mB0, b1 = mB1;
            if (kk < 3) {
                mA0 = mr0[(2 * kk + 2) * 4 + ml]; mA1 = mr0[(2 * kk + 3) * 4 + ml];
                mB0 = mr1[(2 * kk + 2) * 4 + ml]; mB1 = mr1[(2 * kk + 3) * 4 + ml];
            }
            int n0i = 2 * kk, n1i = 2 * kk + 1;
            float p00 = __expf(s[n0i][0]), p01 = __expf(s[n0i][1]);
            float p10 = __expf(s[n0i][2]), p11 = __expf(s[n0i][3]);
            float q00 = __expf(s[n1i][0]), q01 = __expf(s[n1i][1]);
            float q10 = __expf(s[n1i][2]), q11 = __expf(s[n1i][3]);
            Z0 += (p00 + p01) + (q00 + q01);
            Z1 += (p10 + p11) + (q10 + q11);
            float pm00 = p00 * a0.x, pm01 = p01 * a0.y;
            float pm10 = p10 * b0.x, pm11 = p11 * b0.y;
            float qm00 = q00 * a1.x, qm01 = q01 * a1.y;
            float qm10 = q10 * b1.x, qm11 = q11 * b1.y;
            S0 += (pm00 + pm01) + (qm00 + qm01);
            S1 += (pm10 + pm11) + (qm10 + qm11);
            uint32_t pa[4];
            pa[0] = packh2(pm00, pm01);
            pa[1] = packh2(pm10, pm11);
            pa[2] = packh2(qm00, qm01);
            pa[3] = packh2(qm10, qm11);
#pragma unroll
            for (int etp = 0; etp < 4; etp++) {
                mma16(o[etp * 2 + 0], pa, &vb[etp][0]);
                mma16(o[etp * 2 + 1], pa, &vb[etp][2]);
            }
        }
        __syncthreads();
    }

    Z0 += __shfl_xor_sync(0xffffffffu, Z0, 1); Z0 += __shfl_xor_sync(0xffffffffu, Z0, 2);
    Z1 += __shfl_xor_sync(0xffffffffu, Z1, 1); Z1 += __shfl_xor_sync(0xffffffffu, Z1, 2);
    S0 += __shfl_xor_sync(0xffffffffu, S0, 1); S0 += __shfl_xor_sync(0xffffffffu, S0, 2);
    S1 += __shfl_xor_sync(0xffffffffu, S1, 1); S1 += __shfl_xor_sync(0xffffffffu, S1, 2);

    float d0 = 1.f / (S0 + 1e-6f * Z0);
    float d1 = 1.f / (S1 + 1e-6f * Z1);

    const int n = bh & 7, h = bh >> 3;
    __half* oh0 = go + (size_t)(n * NQ + q0 + warp * 16 + (lane >> 2)) * DD + h * DH;
    __half* oh1 = oh0 + 8 * DD;
#pragma unroll
    for (int et = 0; et < 8; et++) {
        int cc = et * 8 + 2 * (lane & 3);
        *(__half2*)(oh0 + cc) = __floats2half2_rn(o[et][0] * d0, o[et][1] * d0);
        *(__half2*)(oh1 + cc) = __floats2half2_rn(o[et][2] * d1, o[et][3] * d1);
    }
}

// ---------------------------------------------------------------------------
extern "C" void kernel_launch(void* const* d_in, const int* in_sizes, int n_in,
                              void* d_out, int out_size)
{
    const float* q    = (const float*)d_in[0];
    const float* k    = (const float*)d_in[1];
    const float* v    = (const float*)d_in[2];
    const float* mask = (const float*)d_in[3];
    const float* Wq   = (const float*)d_in[4];
    const float* Wk   = (const float*)d_in[5];
    const float* Wv   = (const float*)d_in[6];
    const float* Wo   = (const float*)d_in[7];
    float* out = (float*)d_out;

    __half *pq, *pk, *pv, *po, *par, *pbr, *pcr, *pwr;
    cudaGetSymbolAddress((void**)&pq, g_q);
    cudaGetSymbolAddress((void**)&pk, g_k);
    cudaGetSymbolAddress((void**)&pv, g_v);
    cudaGetSymbolAddress((void**)&po, g_o);
    cudaGetSymbolAddress((void**)&par, g_ar);
    cudaGetSymbolAddress((void**)&pbr, g_br);
    cudaGetSymbolAddress((void**)&pcr, g_cr);
    cudaGetSymbolAddress((void**)&pwr, g_wr);

    cudaFuncSetAttribute(gemm_qkv, cudaFuncAttributeMaxDynamicSharedMemorySize, GEMM_SMEM);
    cudaFuncSetAttribute(gemm_out, cudaFuncAttributeMaxDynamicSharedMemorySize, GEMM_SMEM);

    round_all<<<1024, 256>>>((const float4*)q, (const float4*)k, (const float4*)v,
                             (const float4*)Wq, (const float4*)Wk, (const float4*)Wv,
                             (const float4*)Wo,
                             (__half2*)par, (__half2*)pbr, (__half2*)pcr, (__half2*)pwr);

    gemm_qkv<<<dim3(24, 64), 256, GEMM_SMEM>>>(par, pbr, pcr,
                                    pwr + 0 * DD * DD, pwr + 1 * DD * DD, pwr + 2 * DD * DD,
                                    pq, pk, pv);
    attn<<<dim3(8, 128), 256>>>(pq, pk, pv, mask, po);
    gemm_out<<<dim3(8, 64), 256, GEMM_SMEM>>>(po, pwr + 3 * DD * DD, out);
}

// round 12
// speedup vs baseline: 1.8385x; 1.1040x over previous
#include <cuda_runtime.h>
#include <cuda_fp16.h>
#include <cstdint>

#define N_B 8
#define NQ  1024
#define NK  1024
#define DD  1024
#define HH  16
#define DH  64
#define ELEMS (N_B*NQ*DD)   // 8388608

// Scratch (fp16). g_q: pre-scaled by 1/8, [bh][row][e]. g_k: [bh][key][e].
// g_v: TRANSPOSED [bh][e][key]. g_o: [n][q][h*64+e].
__device__ __half g_q[HH*N_B*NQ*DH];
__device__ __half g_k[HH*N_B*NK*DH];
__device__ __half g_v[HH*N_B*NK*DH];
__device__ __half g_o[ELEMS];
// fp16 copies of GEMM inputs
__device__ __half g_ar[ELEMS];
__device__ __half g_br[ELEMS];
__device__ __half g_cr[ELEMS];
__device__ __half g_wr[4][DD*DD];

__device__ __forceinline__ void mma16(float* c, const uint32_t* a, const uint32_t* b) {
    asm volatile(
        "mma.sync.aligned.m16n8k16.row.col.f32.f16.f16.f32 "
        "{%0,%1,%2,%3}, {%4,%5,%6,%7}, {%8,%9}, {%0,%1,%2,%3};"
        : "+f"(c[0]), "+f"(c[1]), "+f"(c[2]), "+f"(c[3])
        : "r"(a[0]), "r"(a[1]), "r"(a[2]), "r"(a[3]), "r"(b[0]), "r"(b[1]));
}

__device__ __forceinline__ void ldsm4(uint32_t* d, uint32_t addr) {
    asm volatile("ldmatrix.sync.aligned.m8n8.x4.shared.b16 {%0,%1,%2,%3}, [%4];"
        : "=r"(d[0]), "=r"(d[1]), "=r"(d[2]), "=r"(d[3]) : "r"(addr));
}

__device__ __forceinline__ uint32_t s2u(const void* p) {
    return (uint32_t)__cvta_generic_to_shared(p);
}

__device__ __forceinline__ void cpa16(uint32_t dst, const void* src) {
    asm volatile("cp.async.cg.shared.global [%0], [%1], 16;" :: "r"(dst), "l"(src));
}
#define CPA_COMMIT asm volatile("cp.async.commit_group;")
#define CPA_WAIT0  asm volatile("cp.async.wait_group 0;")

// pack two f32 -> fp16x2 register (lo = first arg)
__device__ __forceinline__ uint32_t packh2(float lo, float hi) {
    uint32_t r; asm("cvt.rn.f16x2.f32 %0, %1, %2;" : "=r"(r) : "f"(hi), "f"(lo));
    return r;
}

// ---------------------------------------------------------------------------
// Fused pre-convert fp32 -> fp16: 3 activations + 4 weights in one launch
// ---------------------------------------------------------------------------
#define ACT4 (ELEMS/4)
#define W4   (DD*DD/4)
#define TOT4 (3*ACT4 + 4*W4)

__global__ __launch_bounds__(256) void round_all(
    const float4* __restrict__ q, const float4* __restrict__ k,
    const float4* __restrict__ v, const float4* __restrict__ wq,
    const float4* __restrict__ wk, const float4* __restrict__ wv,
    const float4* __restrict__ wo,
    __half2* __restrict__ ar, __half2* __restrict__ br, __half2* __restrict__ cr,
    __half2* __restrict__ wr)
{
    int i = blockIdx.x * blockDim.x + threadIdx.x;
    int stride = gridDim.x * blockDim.x;
    for (; i < TOT4; i += stride) {
        const float4* src; __half2* dst; int j;
        if (i < 3 * ACT4) {
            int r = i / ACT4; j = i - r * ACT4;
            src = (r == 0) ? q : (r == 1) ? k : v;
            dst = (r == 0) ? ar : (r == 1) ? br : cr;
        } else {
            int t = i - 3 * ACT4;
            int r = t / W4; j = t - r * W4;
            src = (r == 0) ? wq : (r == 1) ? wk : (r == 2) ? wv : wo;
            dst = wr + r * (DD * DD / 2);
        }
        float4 x = src[j];
        __half2 h0 = __floats2half2_rn(x.x, x.y);
        __half2 h1 = __floats2half2_rn(x.z, x.w);
        uint2 u; u.x = *(uint32_t*)&h0; u.y = *(uint32_t*)&h1;
        *(uint2*)(dst + 2 * j) = u;
    }
}

// ---------------------------------------------------------------------------
// fp16 GEMM: C[m,r] = sum_d A[m,d]*W[r,d]  (m16n8k16, f32 accum)
// 256 threads, 8 warps, warp tile 64x32, block tile 128x128.
// 64-k-col stages, 2 smem buffers, ONE __syncthreads per stage.
// ---------------------------------------------------------------------------
#define PH 72
#define GSTG (128 * PH)
#define GEMM_SMEM (2 * 2 * GSTG * 2)       // 73728 bytes

__device__ __forceinline__ void gemm_body(
    const __half* __restrict__ A, const __half* __restrict__ W,
    void* __restrict__ out, int mode, int bx, int by)
{
    extern __shared__ __half hsm[];
    __half* Asb = hsm;
    __half* Bsb = hsm + 2 * GSTG;
    const int tid  = threadIdx.x;
    const int lane = tid & 31, warp = tid >> 5;
    const int wm = warp >> 2, wn = warp & 3;
    const int m0 = by * 128, n0 = bx * 128;

    float c[4][4][4];
#pragma unroll
    for (int a = 0; a < 4; a++)
#pragma unroll
        for (int b = 0; b < 4; b++)
#pragma unroll
            for (int i = 0; i < 4; i++) c[a][b][i] = 0.f;

    const int a_off = (wm * 64 + (lane & 15)) * PH + ((lane >> 4) << 3);
    const int b_off = (wn * 32 + (lane & 7) + ((lane >> 4) << 3)) * PH + (lane & 8);

    auto stage = [&](int t, int s) {
        __half* As = Asb + s * GSTG;
        __half* Bs = Bsb + s * GSTG;
#pragma unroll
        for (int i = 0; i < 4; i++) {
            int ch = tid + i * 256;
            int row = ch >> 3, c16 = (ch & 7) * 8;
            cpa16(s2u(As + row * PH + c16), A + (size_t)(m0 + row) * DD + t * 64 + c16);
            cpa16(s2u(Bs + row * PH + c16), W + (size_t)(n0 + row) * DD + t * 64 + c16);
        }
        CPA_COMMIT;
    };

    stage(0, 0);

    for (int kt = 0; kt < 16; kt++) {
        CPA_WAIT0;
        __syncthreads();
        if (kt + 1 < 16) stage(kt + 1, (kt + 1) & 1);

        const __half* As = Asb + (kt & 1) * GSTG;
        const __half* Bs = Bsb + (kt & 1) * GSTG;
#pragma unroll
        for (int kk = 0; kk < 4; kk++) {
            uint32_t af[4][4];
#pragma unroll
            for (int mt = 0; mt < 4; mt++)
                ldsm4(af[mt], s2u(As + a_off + mt * 16 * PH + kk * 16));
#pragma unroll
            for (int ng = 0; ng < 2; ng++) {
                uint32_t bf[4];
                ldsm4(bf, s2u(Bs + b_off + ng * 16 * PH + kk * 16));
#pragma unroll
                for (int mt = 0; mt < 4; mt++) {
                    mma16(c[mt][ng * 2 + 0], af[mt], &bf[0]);
                    mma16(c[mt][ng * 2 + 1], af[mt], &bf[2]);
                }
            }
        }
    }

#pragma unroll
    for (int mt = 0; mt < 4; mt++) {
        int mr = m0 + wm * 64 + mt * 16 + (lane >> 2);
#pragma unroll
        for (int nt = 0; nt < 4; nt++) {
            int nc = n0 + wn * 32 + nt * 8 + 2 * (lane & 3);
#pragma unroll
            for (int half = 0; half < 2; half++) {
                int m = mr + half * 8;
                float v0 = c[mt][nt][half * 2 + 0];
                float v1 = c[mt][nt][half * 2 + 1];
                if (mode == 1) {
                    *(float2*)((float*)out + (size_t)m * DD + nc) = make_float2(v0, v1);
                } else if (mode == 0 || mode == 2) {
                    float sc = (mode == 0) ? 0.125f : 1.0f;
                    size_t idx = ((size_t)((nc >> 6) * N_B + (m >> 10)) << 16)
                               + (size_t)((m & 1023) * 64 + (nc & 63));
                    *(__half2*)((__half*)out + idx) = __floats2half2_rn(v0 * sc, v1 * sc);
                } else { // mode 3: V transposed [bh][e][key]
                    int key = m & 1023, n = m >> 10;
#pragma unroll
                    for (int cc = 0; cc < 2; cc++) {
                        int r = nc + cc, h = r >> 6, e = r & 63;
                        size_t idx = ((size_t)(h * N_B + n) << 16) + (size_t)e * NK + key;
                        ((__half*)out)[idx] = __float2half_rn(cc ? v1 : v0);
                    }
                }
            }
        }
    }
}

__global__ __launch_bounds__(256, 2) void gemm_qkv(
    const __half* __restrict__ Aq, const __half* __restrict__ Ak, const __half* __restrict__ Av,
    const __half* __restrict__ Wq, const __half* __restrict__ Wk, const __half* __restrict__ Wv,
    __half* __restrict__ oq, __half* __restrict__ ok, __half* __restrict__ ov)
{
    const int which = blockIdx.x >> 3;
    const int bx = blockIdx.x & 7;
    const __half* A = (which == 0) ? Aq : (which == 1) ? Ak : Av;
    const __half* W = (which == 0) ? Wq : (which == 1) ? Wk : Wv;
    __half* out    = (which == 0) ? oq : (which == 1) ? ok : ov;
    const int mode = (which == 0) ? 0 : (which == 1) ? 2 : 3;
    gemm_body(A, W, out, mode, bx, blockIdx.y);
}

__global__ __launch_bounds__(256, 2) void gemm_out(
    const __half* __restrict__ A, const __half* __restrict__ W,
    float* __restrict__ out)
{
    gemm_body(A, W, out, 1, blockIdx.x, blockIdx.y);
}

// ---------------------------------------------------------------------------
// Flash-style attention, fp16 mma, no online max.
// 256 threads, block = 128 q-rows of one (h,n), warp = 16 rows.
// K, V AND MASK all double-buffered via cp.async (mask 32KB/tile).
// ---------------------------------------------------------------------------
#define PH2 72
#define KVH (64 * PH2)                  // halfs per K or V buffer
#define MPITCH 68                       // floats; 272B rows (16B-aligned)
#define MBUF (128 * MPITCH)             // floats per mask buffer
#define ATTN_SMEM (4 * KVH * 2 + 2 * MBUF * 4)   // 36864 + 69632 = 106496 B

__global__ __launch_bounds__(256, 2) void attn(
    const __half* __restrict__ gq, const __half* __restrict__ gk,
    const __half* __restrict__ gvt, const float* __restrict__ mask,
    __half* __restrict__ go)
{
    extern __shared__ __half hsm[];
    __half* Kb = hsm;                    // [2][KVH]
    __half* Vb = hsm + 2 * KVH;          // [2][KVH]
    float*  Mb = (float*)(hsm + 4 * KVH);// [2][MBUF]

    const int tid  = threadIdx.x;
    const int lane = tid & 31, warp = tid >> 5;
    const int bh = blockIdx.y;
    const int q0 = blockIdx.x * 128;
    const size_t hb = (size_t)bh * (NQ * DH);

    // Q fragments direct from global (fp16, pre-scaled)
    uint32_t qa[4][4];
    {
        const __half* qr0 = gq + hb + (size_t)(q0 + warp * 16 + (lane >> 2)) * DH;
        const __half* qr1 = qr0 + 8 * DH;
        const int cl = 2 * (lane & 3);
#pragma unroll
        for (int kk = 0; kk < 4; kk++) {
            qa[kk][0] = *(const uint32_t*)(qr0 + kk * 16 + cl);
            qa[kk][1] = *(const uint32_t*)(qr1 + kk * 16 + cl);
            qa[kk][2] = *(const uint32_t*)(qr0 + kk * 16 + cl + 8);
            qa[kk][3] = *(const uint32_t*)(qr1 + kk * 16 + cl + 8);
        }
    }

    float o[8][4];
#pragma unroll
    for (int et = 0; et < 8; et++)
#pragma unroll
        for (int i = 0; i < 4; i++) o[et][i] = 0.f;

    float Z0 = 0.f, Z1 = 0.f, S0 = 0.f, S1 = 0.f;

    const float* mblk = mask + (size_t)bh * ((size_t)NQ * NK) + (size_t)q0 * NK;

    const int kb_off = ((lane & 7) + ((lane >> 4) << 3)) * PH2 + (lane & 8);

    const __half* ksrc_b = gk + hb;
    const __half* vsrc_b = gvt + hb;

    // stage K(8KB as halfs), V, and mask tile (32KB) for kt into buffer b
    auto stage = [&](int kt, int b) {
        __half* Kd = Kb + b * KVH;
        __half* Vd = Vb + b * KVH;
        float*  Md = Mb + b * MBUF;
        const __half* ks = ksrc_b + (size_t)kt * 64 * DH;
        const __half* vs = vsrc_b + kt * 64;
        const float*  ms = mblk + kt * 64;
#pragma unroll
        for (int i = 0; i < 2; i++) {
            int ch = tid + i * 256;               // 0..511
            int row = ch >> 3, c16 = (ch & 7) * 8;
            cpa16(s2u(Kd + row * PH2 + c16), ks + row * DH + c16);
            cpa16(s2u(Vd + row * PH2 + c16), vs + (size_t)row * NK + c16);
        }
#pragma unroll
        for (int i = 0; i < 8; i++) {
            int ch = tid + i * 256;               // 0..2047
            int row = ch >> 4, c4 = (ch & 15) * 4;
            cpa16(s2u(Md + row * MPITCH + c4), ms + (size_t)row * NK + c4);
        }
        CPA_COMMIT;
    };

    stage(0, 0);

    for (int kt = 0; kt < 16; kt++) {
        const int buf = kt & 1;
        CPA_WAIT0;
        __syncthreads();
        if (kt < 15) stage(kt + 1, buf ^ 1);

        const __half* Ks = Kb + buf * KVH;
        const __half* Vt = Vb + buf * KVH;
        const float*  Ms = Mb + buf * MBUF;

        // S = Q K^T (scale folded into Q)
        float s[8][4];
#pragma unroll
        for (int nt = 0; nt < 8; nt++)
#pragma unroll
            for (int i = 0; i < 4; i++) s[nt][i] = 0.f;
#pragma unroll
        for (int kk = 0; kk < 4; kk++) {
#pragma unroll
            for (int ntp = 0; ntp < 4; ntp++) {
                uint32_t bf[4];
                ldsm4(bf, s2u(Ks + kb_off + ntp * 16 * PH2 + kk * 16));
                mma16(s[ntp * 2 + 0], qa[kk], &bf[0]);
                mma16(s[ntp * 2 + 1], qa[kk], &bf[2]);
            }
        }

        // PV in 4 k16-slices; mask from smem
        const float* ms0 = Ms + (warp * 16 + (lane >> 2)) * MPITCH + 2 * (lane & 3);
        const float* ms1 = ms0 + 8 * MPITCH;
#pragma unroll
        for (int kk = 0; kk < 4; kk++) {
            uint32_t vb[4][4];
#pragma unroll
            for (int etp = 0; etp < 4; etp++)
                ldsm4(vb[etp], s2u(Vt + kb_off + etp * 16 * PH2 + kk * 16));

            int n0i = 2 * kk, n1i = 2 * kk + 1;
            float2 a0 = *(const float2*)(ms0 + n0i * 8);
            float2 a1 = *(const float2*)(ms0 + n1i * 8);
            float2 b0 = *(const float2*)(ms1 + n0i * 8);
            float2 b1 = *(const float2*)(ms1 + n1i * 8);
            float p00 = __expf(s[n0i][0]), p01 = __expf(s[n0i][1]);
            float p10 = __expf(s[n0i][2]), p11 = __expf(s[n0i][3]);
            float q00 = __expf(s[n1i][0]), q01 = __expf(s[n1i][1]);
            float q10 = __expf(s[n1i][2]), q11 = __expf(s[n1i][3]);
            Z0 += (p00 + p01) + (q00 + q01);
            Z1 += (p10 + p11) + (q10 + q11);
            float pm00 = p00 * a0.x, pm01 = p01 * a0.y;
            float pm10 = p10 * b0.x, pm11 = p11 * b0.y;
            float qm00 = q00 * a1.x, qm01 = q01 * a1.y;
            float qm10 = q10 * b1.x, qm11 = q11 * b1.y;
            S0 += (pm00 + pm01) + (qm00 + qm01);
            S1 += (pm10 + pm11) + (qm10 + qm11);
            uint32_t pa[4];
            pa[0] = packh2(pm00, pm01);
            pa[1] = packh2(pm10, pm11);
            pa[2] = packh2(qm00, qm01);
            pa[3] = packh2(qm10, qm11);
#pragma unroll
            for (int etp = 0; etp < 4; etp++) {
                mma16(o[etp * 2 + 0], pa, &vb[etp][0]);
                mma16(o[etp * 2 + 1], pa, &vb[etp][2]);
            }
        }
        __syncthreads();
    }

    Z0 += __shfl_xor_sync(0xffffffffu, Z0, 1); Z0 += __shfl_xor_sync(0xffffffffu, Z0, 2);
    Z1 += __shfl_xor_sync(0xffffffffu, Z1, 1); Z1 += __shfl_xor_sync(0xffffffffu, Z1, 2);
    S0 += __shfl_xor_sync(0xffffffffu, S0, 1); S0 += __shfl_xor_sync(0xffffffffu, S0, 2);
    S1 += __shfl_xor_sync(0xffffffffu, S1, 1); S1 += __shfl_xor_sync(0xffffffffu, S1, 2);

    float d0 = 1.f / (S0 + 1e-6f * Z0);
    float d1 = 1.f / (S1 + 1e-6f * Z1);

    const int n = bh & 7, h = bh >> 3;
    __half* oh0 = go + (size_t)(n * NQ + q0 + warp * 16 + (lane >> 2)) * DD + h * DH;
    __half* oh1 = oh0 + 8 * DD;
#pragma unroll
    for (int et = 0; et < 8; et++) {
        int cc = et * 8 + 2 * (lane & 3);
        *(__half2*)(oh0 + cc) = __floats2half2_rn(o[et][0] * d0, o[et][1] * d0);
        *(__half2*)(oh1 + cc) = __floats2half2_rn(o[et][2] * d1, o[et][3] * d1);
    }
}

// ---------------------------------------------------------------------------
extern "C" void kernel_launch(void* const* d_in, const int* in_sizes, int n_in,
                              void* d_out, int out_size)
{
    const float* q    = (const float*)d_in[0];
    const float* k    = (const float*)d_in[1];
    const float* v    = (const float*)d_in[2];
    const float* mask = (const float*)d_in[3];
    const float* Wq   = (const float*)d_in[4];
    const float* Wk   = (const float*)d_in[5];
    const float* Wv   = (const float*)d_in[6];
    const float* Wo   = (const float*)d_in[7];
    float* out = (float*)d_out;

    __half *pq, *pk, *pv, *po, *par, *pbr, *pcr, *pwr;
    cudaGetSymbolAddress((void**)&pq, g_q);
    cudaGetSymbolAddress((void**)&pk, g_k);
    cudaGetSymbolAddress((void**)&pv, g_v);
    cudaGetSymbolAddress((void**)&po, g_o);
    cudaGetSymbolAddress((void**)&par, g_ar);
    cudaGetSymbolAddress((void**)&pbr, g_br);
    cudaGetSymbolAddress((void**)&pcr, g_cr);
    cudaGetSymbolAddress((void**)&pwr, g_wr);

    cudaFuncSetAttribute(gemm_qkv, cudaFuncAttributeMaxDynamicSharedMemorySize, GEMM_SMEM);
    cudaFuncSetAttribute(gemm_out, cudaFuncAttributeMaxDynamicSharedMemorySize, GEMM_SMEM);
    cudaFuncSetAttribute(attn,     cudaFuncAttributeMaxDynamicSharedMemorySize, ATTN_SMEM);

    round_all<<<1024, 256>>>((const float4*)q, (const float4*)k, (const float4*)v,
                             (const float4*)Wq, (const float4*)Wk, (const float4*)Wv,
                             (const float4*)Wo,
                             (__half2*)par, (__half2*)pbr, (__half2*)pcr, (__half2*)pwr);

    gemm_qkv<<<dim3(24, 64), 256, GEMM_SMEM>>>(par, pbr, pcr,
                                    pwr + 0 * DD * DD, pwr + 1 * DD * DD, pwr + 2 * DD * DD,
                                    pq, pk, pv);
    attn<<<dim3(8, 128), 256, ATTN_SMEM>>>(pq, pk, pv, mask, po);
    gemm_out<<<dim3(8, 64), 256, GEMM_SMEM>>>(po, pwr + 3 * DD * DD, out);
}